// round 14
// baseline (speedup 1.0000x reference)
#include <cuda_runtime.h>

#define N_COL 256
#define N_ROW 256
#define N_CELLS (N_COL * N_ROW)
#define N_WORDS (N_CELLS / 32)          // 2048 bitmask words (8 KB)
#define N_AGENT_PTS (64 * 1001)         // 64064
#define N_PTS4 (N_AGENT_PTS / 4)        // 16016
#define BATCH 512
#define N_M4 (N_CELLS / 4)              // 16384 float4s per batch row
#define BPT 4                           // batch rows per apply thread

#define GRID_BLOCKS (N_M4 * (BATCH / BPT) / 256)   // 8192
#define SCAT_BLOCKS 63                  // ceil(16016/256); all in wave 1
#define N_FLAGS 64
#define FLAG_STRIDE 32                  // 128 B apart -> distinct L2 sectors

// Parity double-buffered bitmask + counts (buffer e&1 zeroed during call e-1).
__device__ __align__(16) unsigned int g_mask[2][N_WORDS];
__device__ unsigned int g_cnt[2];
// Spread completion flags: flag[i*32] holds the tag of the last finished epoch.
// Monotonic values, never reset -> replay-safe.
__device__ unsigned int g_flags[N_FLAGS * FLAG_STRIDE];
// Monotonic counters (never reset -> graph-replay deterministic).
__device__ unsigned int g_blk_arrive;   // +GRID_BLOCKS per call
__device__ unsigned int g_scat_done;    // +SCAT_BLOCKS per call

__device__ __forceinline__ unsigned int ld_vol(const unsigned int* p) {
    unsigned int v;
    asm volatile("ld.volatile.global.u32 %0, [%1];" : "=r"(v) : "l"(p) : "memory");
    return v;
}

__device__ __forceinline__ bool mark_point(float x, float y, unsigned int par) {
    float fx = x * (float)N_COL;
    float fy = y * (float)N_ROW;
    float cx = floorf(fx);
    float cy = floorf(fy);
    float rx = fx - cx;
    float ry = fy - cy;
    bool in_box = (rx >= 0.25f) && (rx <= 0.75f) &&
                  (ry >= 0.25f) && (ry <= 0.75f);
    if (!in_box) return false;
    int ix = min(max((int)cx, 0), N_COL - 1);
    int iy = min(max((int)cy, 0), N_ROW - 1);
    // rot90 CCW folded in: (ix,iy) -> k = (255-iy)*256 + ix
    int k = (N_ROW - 1 - iy) * N_COL + ix;
    unsigned int bit = 1u << (k & 31);
    unsigned int old = atomicOr(&g_mask[par][k >> 5], bit);
    return !(old & bit);
}

__global__ void __launch_bounds__(256)
k_fused(const float4* __restrict__ ax4, const float4* __restrict__ ay4,
        const float4* __restrict__ in, float4* __restrict__ out) {
    __shared__ unsigned int s_epoch;
    const int t = threadIdx.x;
    const int b = blockIdx.x;

    if (t == 0) s_epoch = atomicAdd(&g_blk_arrive, 1u) / GRID_BLOCKS;
    __syncthreads();
    const unsigned int epoch = s_epoch;
    const unsigned int par = epoch & 1u;
    const unsigned int tag = epoch + 1u;                 // monotonic

    // ---- scatter duty: blocks 0..62, 4 points/thread, buffer pre-zeroed ----
    if (b < SCAT_BLOCKS) {
        const int j = b * 256 + t;
        int nfirst = 0;
        if (j < N_PTS4) {
            float4 x = ax4[j];
            float4 y = ay4[j];
            nfirst += mark_point(x.x, y.x, par) ? 1 : 0;
            nfirst += mark_point(x.y, y.y, par) ? 1 : 0;
            nfirst += mark_point(x.z, y.z, par) ? 1 : 0;
            nfirst += mark_point(x.w, y.w, par) ? 1 : 0;
        }
        #pragma unroll
        for (int o = 16; o > 0; o >>= 1)
            nfirst += __shfl_down_sync(0xffffffffu, nfirst, o);
        if ((t & 31) == 0 && nfirst)
            atomicAdd(&g_cnt[par], (unsigned int)nfirst);
        __syncthreads();
        if (t == 0) {
            __threadfence();                             // publish my atomics
            unsigned int old = atomicAdd(&g_scat_done, 1u);
            if (old == tag * SCAT_BLOCKS - 1u) {         // I am the last block
                __threadfence();
                #pragma unroll
                for (int f = 0; f < N_FLAGS; f++)        // fan-out, spread addrs
                    __stcg(&g_flags[f * FLAG_STRIDE], tag);
            }
        }
    }
    // ---- zero duty: blocks 63..70 prep the other parity for the next call ----
    else if (b < 63 + 8) {
        g_mask[1u - par][(b - 63) * 256 + t] = 0u;
        if (b == 63 && t == 0) g_cnt[1u - par] = 0u;
    }

    // ---- apply: all 8192 blocks ----
    const int tid = b * 256 + t;
    const int m = tid & (N_M4 - 1);      // float4 index within a batch row
    const int g = tid >> 14;             // batch group (0..127)
    const long base = (long)(g * BPT) * N_M4 + m;
    const float4* p = in + base;
    float4* q = out + base;

    // 4 independent streaming loads — in flight before the poll
    float4 v0 = __ldcs(p + 0 * N_M4);
    float4 v1 = __ldcs(p + 1 * N_M4);
    float4 v2 = __ldcs(p + 2 * N_M4);
    float4 v3 = __ldcs(p + 3 * N_M4);

    // poll my spread flag (~128 pollers per address, off the atomics' path)
    if (t == 0) {
        const unsigned int* myflag = &g_flags[(b & (N_FLAGS - 1)) * FLAG_STRIDE];
        while ((int)(ld_vol(myflag) - tag) < 0) __nanosleep(64);
        __threadfence();
    }
    __syncthreads();

    const unsigned int cnt = __ldcg(&g_cnt[par]);
    const float scale = (float)N_CELLS / (float)(N_CELLS - cnt);

    // mask word via L2 (written by other blocks this kernel -> bypass L1)
    unsigned int word = __ldcg(&g_mask[par][m >> 3]);
    unsigned int bits = (word >> ((m & 7) * 4)) & 0xFu;

    float sx = (bits & 1u) ? 0.0f : scale;
    float sy = (bits & 2u) ? 0.0f : scale;
    float sz = (bits & 4u) ? 0.0f : scale;
    float sw = (bits & 8u) ? 0.0f : scale;

    v0.x *= sx; v0.y *= sy; v0.z *= sz; v0.w *= sw;
    v1.x *= sx; v1.y *= sy; v1.z *= sz; v1.w *= sw;
    v2.x *= sx; v2.y *= sy; v2.z *= sz; v2.w *= sw;
    v3.x *= sx; v3.y *= sy; v3.z *= sz; v3.w *= sw;

    __stcs(q + 0 * N_M4, v0);
    __stcs(q + 1 * N_M4, v1);
    __stcs(q + 2 * N_M4, v2);
    __stcs(q + 3 * N_M4, v3);
}

extern "C" void kernel_launch(void* const* d_in, const int* in_sizes, int n_in,
                              void* d_out, int out_size) {
    const float* input = (const float*)d_in[0];
    const float* agents_x = (const float*)d_in[1];
    const float* agents_y = (const float*)d_in[2];
    float* out = (float*)d_out;

    k_fused<<<GRID_BLOCKS, 256>>>((const float4*)agents_x,
                                  (const float4*)agents_y,
                                  (const float4*)input, (float4*)out);
}

// round 15
// speedup vs baseline: 1.0464x; 1.0464x over previous
#include <cuda_runtime.h>

#define N_COL 256
#define N_ROW 256
#define N_CELLS (N_COL * N_ROW)
#define N_WORDS (N_CELLS / 32)          // 2048 bitmask words (8 KB)
#define N_AGENT_PTS (64 * 1001)         // 64064
#define N_PTS4 (N_AGENT_PTS / 4)        // 16016
#define BATCH 512
#define N_M4 (N_CELLS / 4)              // 16384 float4s per batch row
#define BPT 8                           // batch rows per apply thread

#define SCAT_BLOCKS 63                  // ceil(16016/256)
#define APPLY_BLOCKS (N_M4 * (BATCH / BPT) / 256)   // 4096

// Parity double-buffered bitmask + counts. Call with epoch e uses buffer
// e&1, zeroed during call e-1's apply (kernel boundary publishes it).
// Zero-initialized at module load -> epoch 0 valid.
__device__ __align__(16) unsigned int g_mask[2][N_WORDS];
__device__ unsigned int g_cnt[2];
__device__ unsigned int g_par_pub;      // parity of the current call
// Monotonic scatter call counter (never reset -> graph-replay deterministic).
__device__ unsigned int g_scat_calls;

__device__ __forceinline__ bool mark_point(float x, float y, unsigned int par) {
    float fx = x * (float)N_COL;
    float fy = y * (float)N_ROW;
    float cx = floorf(fx);
    float cy = floorf(fy);
    float rx = fx - cx;
    float ry = fy - cy;
    bool in_box = (rx >= 0.25f) && (rx <= 0.75f) &&
                  (ry >= 0.25f) && (ry <= 0.75f);
    if (!in_box) return false;
    int ix = min(max((int)cx, 0), N_COL - 1);
    int iy = min(max((int)cy, 0), N_ROW - 1);
    // rot90 CCW folded in: (ix,iy) -> k = (255-iy)*256 + ix
    int k = (N_ROW - 1 - iy) * N_COL + ix;
    unsigned int bit = 1u << (k & 31);
    unsigned int old = atomicOr(&g_mask[par][k >> 5], bit);
    return !(old & bit);                // first toucher this call
}

// Scatter: 63 blocks, 4 agent points per thread via float4 loads.
// No init phase, no barrier — buffer pre-zeroed by previous apply.
__global__ void __launch_bounds__(256)
k_scatter(const float4* __restrict__ ax4, const float4* __restrict__ ay4) {
    __shared__ unsigned int s_epoch;
    const int t = threadIdx.x;
    if (t == 0) s_epoch = atomicAdd(&g_scat_calls, 1u) / SCAT_BLOCKS;
    __syncthreads();
    const unsigned int par = s_epoch & 1u;

    if (blockIdx.x == 0 && t == 1) g_par_pub = par;   // publish for apply

    const int j = blockIdx.x * 256 + t;
    int nfirst = 0;
    if (j < N_PTS4) {
        float4 x = ax4[j];
        float4 y = ay4[j];
        nfirst += mark_point(x.x, y.x, par) ? 1 : 0;
        nfirst += mark_point(x.y, y.y, par) ? 1 : 0;
        nfirst += mark_point(x.z, y.z, par) ? 1 : 0;
        nfirst += mark_point(x.w, y.w, par) ? 1 : 0;
    }
    // warp-aggregated count: one atomic per warp
    #pragma unroll
    for (int o = 16; o > 0; o >>= 1)
        nfirst += __shfl_down_sync(0xffffffffu, nfirst, o);
    if ((t & 31) == 0 && nfirst)
        atomicAdd(&g_cnt[par], (unsigned int)nfirst);
}

// Apply: out = in * mask * scale. BPT=8 -> 128 B in flight per thread.
// Plain L1-cached mask reads are safe (L1 flushed at launch boundary).
// Side duty: zero the OTHER parity's buffer for the next call.
__global__ void __launch_bounds__(256)
k_apply(const float4* __restrict__ in, float4* __restrict__ out) {
    const int t = threadIdx.x;
    const int b = blockIdx.x;
    const int tid = b * 256 + t;

    const unsigned int par = g_par_pub;               // set by this call's scatter

    // zero next call's buffer + count slot
    if (b < 8) g_mask[1u - par][b * 256 + t] = 0u;
    if (b == 8 && t == 0) g_cnt[1u - par] = 0u;

    const int m = tid & (N_M4 - 1);      // float4 index within a batch row
    const int g = tid >> 14;             // batch group (0..63)
    const long base = (long)(g * BPT) * N_M4 + m;
    const float4* p = in + base;
    float4* q = out + base;

    // 8 independent read-once streaming loads (MLP=8)
    float4 v0 = __ldcs(p + 0 * N_M4);
    float4 v1 = __ldcs(p + 1 * N_M4);
    float4 v2 = __ldcs(p + 2 * N_M4);
    float4 v3 = __ldcs(p + 3 * N_M4);
    float4 v4 = __ldcs(p + 4 * N_M4);
    float4 v5 = __ldcs(p + 5 * N_M4);
    float4 v6 = __ldcs(p + 6 * N_M4);
    float4 v7 = __ldcs(p + 7 * N_M4);

    unsigned int cnt = g_cnt[par];
    float scale = __fdividef((float)N_CELLS, (float)(N_CELLS - cnt));

    unsigned int word = g_mask[par][m >> 3];          // 4B, L1-resident
    unsigned int bits = (word >> ((m & 7) * 4)) & 0xFu;

    float sx = (bits & 1u) ? 0.0f : scale;
    float sy = (bits & 2u) ? 0.0f : scale;
    float sz = (bits & 4u) ? 0.0f : scale;
    float sw = (bits & 8u) ? 0.0f : scale;

    v0.x *= sx; v0.y *= sy; v0.z *= sz; v0.w *= sw;
    v1.x *= sx; v1.y *= sy; v1.z *= sz; v1.w *= sw;
    v2.x *= sx; v2.y *= sy; v2.z *= sz; v2.w *= sw;
    v3.x *= sx; v3.y *= sy; v3.z *= sz; v3.w *= sw;
    v4.x *= sx; v4.y *= sy; v4.z *= sz; v4.w *= sw;
    v5.x *= sx; v5.y *= sy; v5.z *= sz; v5.w *= sw;
    v6.x *= sx; v6.y *= sy; v6.z *= sz; v6.w *= sw;
    v7.x *= sx; v7.y *= sy; v7.z *= sz; v7.w *= sw;

    // streaming stores: evict-first, drain to DRAM early
    __stcs(q + 0 * N_M4, v0);
    __stcs(q + 1 * N_M4, v1);
    __stcs(q + 2 * N_M4, v2);
    __stcs(q + 3 * N_M4, v3);
    __stcs(q + 4 * N_M4, v4);
    __stcs(q + 5 * N_M4, v5);
    __stcs(q + 6 * N_M4, v6);
    __stcs(q + 7 * N_M4, v7);
}

extern "C" void kernel_launch(void* const* d_in, const int* in_sizes, int n_in,
                              void* d_out, int out_size) {
    const float* input = (const float*)d_in[0];
    const float* agents_x = (const float*)d_in[1];
    const float* agents_y = (const float*)d_in[2];
    float* out = (float*)d_out;

    k_scatter<<<SCAT_BLOCKS, 256>>>((const float4*)agents_x,
                                    (const float4*)agents_y);
    k_apply<<<APPLY_BLOCKS, 256>>>((const float4*)input, (float4*)out);
}